// round 1
// baseline (speedup 1.0000x reference)
#include <cuda_runtime.h>
#include <cuda_bf16.h>
#include <math.h>

// ---------------- problem constants ----------------
#define BATCH   8
#define SEQ     2048
#define HDIM    512
#define DPROJ   2192      // 2*D_INNER + CONV_DIM split parts: z(1024)|xBC(1152)|dt(16)
#define DINNER  1024
#define DSTATE  64
#define NHEADS  16
#define HEADD   64
#define CONVD   1152      // D_INNER + 2*D_STATE
#define ML      (BATCH*SEQ)   // 16384 rows
#define EPSLN   1e-5f

// ---------------- device scratch (no allocation allowed) ----------------
__device__ float g_x0 [ML*HDIM];
__device__ float g_h  [ML*HDIM];
__device__ float g_hf [ML*HDIM];
__device__ float g_zx0[ML*DPROJ];
__device__ float g_zx1[ML*DPROJ];
__device__ float g_xc0[ML*CONVD];
__device__ float g_xc1[ML*CONVD];
__device__ float g_dt0[ML*NHEADS];
__device__ float g_dt1[ML*NHEADS];
__device__ float g_dA0[ML*NHEADS];
__device__ float g_dA1[ML*NHEADS];
__device__ float g_y0 [ML*DINNER];
__device__ float g_y1 [ML*DINNER];
__device__ float g_d0 [ML*HDIM];
__device__ float g_d1 [ML*HDIM];
__device__ float g_cb [ML*DINNER];
__device__ float g_ot [ML*HDIM];
__device__ float g_pl [BATCH*2*HDIM];

// ---------------- GEMM: C[m,n] = sum_k A[m,k]*W[n,k] (+bias[n]) ----------------
// A: (M,K) row-major, W: (N,K) row-major. M % 128 == 0, K % 16 == 0, N arbitrary.
__global__ __launch_bounds__(256) void sgemm_nt(
    const float* __restrict__ A, const float* __restrict__ W,
    const float* __restrict__ bias, float* __restrict__ C,
    int M, int N, int K)
{
    __shared__ __align__(16) float As[16][128];
    __shared__ __align__(16) float Ws[16][64];
    const int tid = threadIdx.x;
    const int bm = blockIdx.y * 128;
    const int bn = blockIdx.x * 64;

    const int ar = tid >> 1;          // 0..127
    const int ak = (tid & 1) * 8;     // 0 or 8
    const int wr = tid >> 2;          // 0..63
    const int wk = (tid & 3) * 4;     // 0,4,8,12
    const bool wv = (bn + wr) < N;

    const float* Ag = A + (size_t)(bm + ar) * K + ak;
    const float* Wg = W + (size_t)(bn + wr) * K + wk;

    const int ty = tid >> 4;          // 0..15 -> 8 rows each
    const int tx = tid & 15;          // 0..15 -> 4 cols each

    float acc[8][4];
#pragma unroll
    for (int i = 0; i < 8; i++)
#pragma unroll
        for (int j = 0; j < 4; j++) acc[i][j] = 0.f;

    for (int k0 = 0; k0 < K; k0 += 16) {
        float4 a0 = *(const float4*)(Ag + k0);
        float4 a1 = *(const float4*)(Ag + k0 + 4);
        float4 w0 = wv ? *(const float4*)(Wg + k0) : make_float4(0.f, 0.f, 0.f, 0.f);
        __syncthreads();
        As[ak+0][ar] = a0.x; As[ak+1][ar] = a0.y; As[ak+2][ar] = a0.z; As[ak+3][ar] = a0.w;
        As[ak+4][ar] = a1.x; As[ak+5][ar] = a1.y; As[ak+6][ar] = a1.z; As[ak+7][ar] = a1.w;
        Ws[wk+0][wr] = w0.x; Ws[wk+1][wr] = w0.y; Ws[wk+2][wr] = w0.z; Ws[wk+3][wr] = w0.w;
        __syncthreads();
#pragma unroll
        for (int kk = 0; kk < 16; kk++) {
            float4 av0 = *(const float4*)&As[kk][ty*8];
            float4 av1 = *(const float4*)&As[kk][ty*8+4];
            float4 wf  = *(const float4*)&Ws[kk][tx*4];
            float am[8] = {av0.x,av0.y,av0.z,av0.w,av1.x,av1.y,av1.z,av1.w};
            float wm[4] = {wf.x, wf.y, wf.z, wf.w};
#pragma unroll
            for (int i = 0; i < 8; i++)
#pragma unroll
                for (int j = 0; j < 4; j++)
                    acc[i][j] += am[i] * wm[j];
        }
    }
#pragma unroll
    for (int i = 0; i < 8; i++) {
        int m = bm + ty*8 + i;
#pragma unroll
        for (int j = 0; j < 4; j++) {
            int n = bn + tx*4 + j;
            if (n < N)
                C[(size_t)m * N + n] = acc[i][j] + (bias ? bias[n] : 0.f);
        }
    }
}

// ---------------- embedding gather ----------------
__global__ void gather_embed(const int* __restrict__ tok,
                             const float* __restrict__ emb,
                             float* __restrict__ x0)
{
    int x = blockIdx.x * 256 + threadIdx.x;       // ML*512 threads
    int c = x & 511;
    int m = x >> 9;
    x0[x] = emb[(size_t)tok[m] * HDIM + c];
}

// ---------------- length-conditioned flip: dst[b,t,:] = src[b,idx(t),:] ----------------
__global__ void flip_kernel(const float* __restrict__ src, float* __restrict__ dst,
                            const int* __restrict__ lens)
{
    int x = blockIdx.x * 256 + threadIdx.x;       // ML*512
    int c = x & 511;
    int bl = x >> 9;
    int t = bl & (SEQ - 1);
    int b = bl >> 11;
    int len = lens[b];
    int tt = (t < len) ? (len - 1 - t) : t;
    dst[x] = src[((size_t)(b * SEQ + tt) << 9) + c];
}

// ---------------- depthwise causal conv (k=4) + bias + silu over xBC slice ----------------
__global__ void conv_kernel(const float* __restrict__ zx, const float* __restrict__ w,
                            const float* __restrict__ bias, float* __restrict__ xc)
{
    int x = blockIdx.x * 256 + threadIdx.x;       // ML*CONVD
    int c = x % CONVD;
    int bl = x / CONVD;
    int t = bl & (SEQ - 1);
    const float* base = zx + (size_t)bl * DPROJ + DINNER + c;
    float acc = bias[c];
#pragma unroll
    for (int j = 0; j < 4; j++) {
        int tau = t - 3 + j;
        if (tau >= 0)
            acc += w[c * 4 + j] * base[(long)(tau - t) * DPROJ];
    }
    xc[x] = acc / (1.f + __expf(-acc));           // silu
}

// ---------------- dt = softplus(dt_raw + bias), dA = exp(-exp(Alog)*dt) ----------------
__global__ void dt_kernel(const float* __restrict__ zx, const float* __restrict__ dtb,
                          const float* __restrict__ Alog,
                          float* __restrict__ dto, float* __restrict__ dAo)
{
    int x = blockIdx.x * 256 + threadIdx.x;       // ML*16
    int h = x & 15;
    int bl = x >> 4;
    float v = zx[(size_t)bl * DPROJ + (DINNER + CONVD) + h] + dtb[h];
    float dt = (v > 20.f) ? v : log1pf(__expf(v));
    dto[x] = dt;
    dAo[x] = __expf(-__expf(Alog[h]) * dt);
}

// ---------------- sequential SSM scan: one (b,head,dir) per block of 64 threads ----------
// state s[p][n], p = threadIdx (HEADD), n = 0..63 in registers.
__global__ __launch_bounds__(64) void scan_kernel(
    const float* __restrict__ xc0, const float* __restrict__ xc1,
    const float* __restrict__ zx0, const float* __restrict__ zx1,
    const float* __restrict__ dtp0, const float* __restrict__ dtp1,
    const float* __restrict__ dAp0, const float* __restrict__ dAp1,
    const float* __restrict__ Dp,   // layer base: Dp[dir*16 + head]
    float* __restrict__ y0, float* __restrict__ y1)
{
    const int d = blockIdx.y;
    const float* xc  = d ? xc1 : xc0;
    const float* zx  = d ? zx1 : zx0;
    const float* dtp = d ? dtp1 : dtp0;
    const float* dAp = d ? dAp1 : dAp0;
    float* y = d ? y1 : y0;

    const int bh = blockIdx.x;        // 0..127
    const int b = bh >> 4;
    const int h = bh & 15;
    const int p = threadIdx.x;        // 0..63
    const float Dv = Dp[d * NHEADS + h];

    float s[64];
#pragma unroll
    for (int n = 0; n < 64; n++) s[n] = 0.f;

    __shared__ __align__(16) float Bs[64];
    __shared__ __align__(16) float Cs[64];

    const size_t rowxc = (size_t)b * SEQ * CONVD;
    const size_t rowzx = (size_t)b * SEQ * DPROJ;

    for (int t = 0; t < SEQ; t++) {
        const size_t oc = rowxc + (size_t)t * CONVD;
        __syncthreads();
        Bs[p] = xc[oc + DINNER + p];
        Cs[p] = xc[oc + DINNER + DSTATE + p];
        __syncthreads();
        float xv = xc[oc + h * HEADD + p];
        int bt = (b * SEQ + t) * NHEADS + h;
        float dt = dtp[bt];
        float dA = dAp[bt];
        float k = dt * xv;
        float acc = 0.f;
#pragma unroll
        for (int n4 = 0; n4 < 64; n4 += 4) {
            float4 Bv = *(const float4*)&Bs[n4];
            float4 Cv = *(const float4*)&Cs[n4];
            s[n4+0] = s[n4+0] * dA + k * Bv.x;  acc += s[n4+0] * Cv.x;
            s[n4+1] = s[n4+1] * dA + k * Bv.y;  acc += s[n4+1] * Cv.y;
            s[n4+2] = s[n4+2] * dA + k * Bv.z;  acc += s[n4+2] * Cv.z;
            s[n4+3] = s[n4+3] * dA + k * Bv.w;  acc += s[n4+3] * Cv.w;
        }
        float yv = acc + Dv * xv;
        float z = zx[rowzx + (size_t)t * DPROJ + h * HEADD + p];
        yv *= z / (1.f + __expf(-z));           // gate with silu(z)
        y[(size_t)(b * SEQ + t) * DINNER + h * HEADD + p] = yv;
    }
}

// ---------------- RMSNorm over 1024, in place ----------------
__global__ __launch_bounds__(256) void rmsnorm_kernel(float* __restrict__ y,
                                                      const float* __restrict__ w)
{
    int row = blockIdx.x;
    float* p = y + (size_t)row * DINNER;
    int tid = threadIdx.x;
    float v[4];
    float ss = 0.f;
#pragma unroll
    for (int i = 0; i < 4; i++) { v[i] = p[tid + i * 256]; ss += v[i] * v[i]; }
#pragma unroll
    for (int o = 16; o; o >>= 1) ss += __shfl_xor_sync(0xffffffffu, ss, o);
    __shared__ float red[8];
    if ((tid & 31) == 0) red[tid >> 5] = ss;
    __syncthreads();
    float tot = 0.f;
#pragma unroll
    for (int i = 0; i < 8; i++) tot += red[i];
    float sc = rsqrtf(tot * (1.f / DINNER) + EPSLN);
#pragma unroll
    for (int i = 0; i < 4; i++)
        p[tid + i * 256] = v[i] * sc * w[tid + i * 256];
}

// ---------------- comb = [fwd | flip(bwd)] ----------------
__global__ void combine_kernel(const float* __restrict__ fwd, const float* __restrict__ bwd,
                               const int* __restrict__ lens, float* __restrict__ comb)
{
    int x = blockIdx.x * 256 + threadIdx.x;       // ML*512
    int c = x & 511;
    int bl = x >> 9;
    int t = bl & (SEQ - 1);
    int b = bl >> 11;
    comb[(size_t)bl * DINNER + c] = fwd[(size_t)bl * HDIM + c];
    int len = lens[b];
    int tt = (t < len) ? (len - 1 - t) : t;
    comb[(size_t)bl * DINNER + HDIM + c] = bwd[((size_t)(b * SEQ + tt)) * HDIM + c];
}

// ---------------- h = LayerNorm(out + h) over 512 ----------------
__global__ __launch_bounds__(128) void addln_kernel(const float* __restrict__ out,
                                                    float* __restrict__ h,
                                                    const float* __restrict__ g,
                                                    const float* __restrict__ bta)
{
    int row = blockIdx.x;
    const float* po = out + (size_t)row * HDIM;
    float* ph = h + (size_t)row * HDIM;
    int tid = threadIdx.x;
    float v[4];
    float sum = 0.f;
#pragma unroll
    for (int i = 0; i < 4; i++) { v[i] = po[tid + i * 128] + ph[tid + i * 128]; sum += v[i]; }
#pragma unroll
    for (int o = 16; o; o >>= 1) sum += __shfl_xor_sync(0xffffffffu, sum, o);
    __shared__ float red[4];
    if ((tid & 31) == 0) red[tid >> 5] = sum;
    __syncthreads();
    float mean = (red[0] + red[1] + red[2] + red[3]) * (1.f / HDIM);
    float vs = 0.f;
#pragma unroll
    for (int i = 0; i < 4; i++) { float dd = v[i] - mean; vs += dd * dd; }
#pragma unroll
    for (int o = 16; o; o >>= 1) vs += __shfl_xor_sync(0xffffffffu, vs, o);
    __syncthreads();
    if ((tid & 31) == 0) red[tid >> 5] = vs;
    __syncthreads();
    float var = (red[0] + red[1] + red[2] + red[3]) * (1.f / HDIM);
    float sc = rsqrtf(var + EPSLN);
#pragma unroll
    for (int i = 0; i < 4; i++) {
        int c = tid + i * 128;
        ph[c] = (v[i] - mean) * sc * g[c] + bta[c];
    }
}

// ---------------- masked mean-pool over time ----------------
__global__ void pool_kernel(const float* __restrict__ enc, const int* __restrict__ lens,
                            float* __restrict__ pooled)
{
    int x = blockIdx.x * 256 + threadIdx.x;       // BATCH*1024
    int c = x & 1023;
    int b = x >> 10;
    int len = lens[b];
    float s = 0.f;
    for (int t = 0; t < len; t++)
        s += enc[((size_t)(b * SEQ + t)) * (2 * HDIM) + c];
    pooled[x] = s / (float)(len > 0 ? len : 1);
}

// ---------------- adapter: tanh(pooled @ W_ad^T + b_ad) ----------------
__global__ void adapter_kernel(const float* __restrict__ pooled, const float* __restrict__ Wad,
                               const float* __restrict__ bad, float* __restrict__ out)
{
    int x = blockIdx.x * 256 + threadIdx.x;       // BATCH*512
    int o = x & 511;
    int b = x >> 9;
    const float* pr = pooled + (size_t)b * (2 * HDIM);
    const float* wr = Wad + (size_t)o * (2 * HDIM);
    float s = bad[o];
    for (int c = 0; c < 2 * HDIM; c++) s += pr[c] * wr[c];
    out[x] = tanhf(s);
}

// ---------------- host launch ----------------
static float* symaddr(const void* s)
{
    void* p = nullptr;
    cudaGetSymbolAddress(&p, s);
    return (float*)p;
}

extern "C" void kernel_launch(void* const* d_in, const int* in_sizes, int n_in,
                              void* d_out, int out_size)
{
    const int*   tok    = (const int*)  d_in[0];
    const int*   lens   = (const int*)  d_in[1];
    const float* emb    = (const float*)d_in[2];
    const float* W_inp  = (const float*)d_in[3];
    const float* b_inp  = (const float*)d_in[4];
    const float* m_Win  = (const float*)d_in[5];
    const float* m_cw   = (const float*)d_in[6];
    const float* m_cb   = (const float*)d_in[7];
    const float* m_dtb  = (const float*)d_in[8];
    const float* m_Alog = (const float*)d_in[9];
    const float* m_D    = (const float*)d_in[10];
    const float* m_norm = (const float*)d_in[11];
    const float* m_Wout = (const float*)d_in[12];
    const float* blk_Wo = (const float*)d_in[13];
    const float* blk_bo = (const float*)d_in[14];
    const float* ln_g   = (const float*)d_in[15];
    const float* ln_b   = (const float*)d_in[16];
    const float* W_enc  = (const float*)d_in[17];
    const float* b_enc  = (const float*)d_in[18];
    const float* W_ad   = (const float*)d_in[19];
    const float* b_ad   = (const float*)d_in[20];
    float* outp = (float*)d_out;

    float* x0  = symaddr(g_x0);
    float* h   = symaddr(g_h);
    float* hf  = symaddr(g_hf);
    float* zx0 = symaddr(g_zx0);
    float* zx1 = symaddr(g_zx1);
    float* xc0 = symaddr(g_xc0);
    float* xc1 = symaddr(g_xc1);
    float* dt0 = symaddr(g_dt0);
    float* dt1 = symaddr(g_dt1);
    float* dA0 = symaddr(g_dA0);
    float* dA1 = symaddr(g_dA1);
    float* y0  = symaddr(g_y0);
    float* y1  = symaddr(g_y1);
    float* dr0 = symaddr(g_d0);
    float* dr1 = symaddr(g_d1);
    float* cb  = symaddr(g_cb);
    float* ot  = symaddr(g_ot);
    float* pl  = symaddr(g_pl);

    const int TPB = 256;
    dim3 gEl(ML * HDIM / TPB);                 // 32768
    dim3 gConv((ML * CONVD) / TPB);            // 73728
    dim3 gDt((ML * NHEADS) / TPB);             // 1024

    // h = emb[tokens] @ W_inp^T + b_inp
    gather_embed<<<gEl, TPB>>>(tok, emb, x0);
    sgemm_nt<<<dim3((HDIM + 63) / 64, ML / 128), 256>>>(x0, W_inp, b_inp, h, ML, HDIM, HDIM);

    for (int i = 0; i < 4; i++) {
        flip_kernel<<<gEl, TPB>>>(h, hf, lens);

        // in-projections (no bias)
        sgemm_nt<<<dim3((DPROJ + 63) / 64, ML / 128), 256>>>(
            h,  m_Win + (size_t)(i * 2 + 0) * DPROJ * HDIM, nullptr, zx0, ML, DPROJ, HDIM);
        sgemm_nt<<<dim3((DPROJ + 63) / 64, ML / 128), 256>>>(
            hf, m_Win + (size_t)(i * 2 + 1) * DPROJ * HDIM, nullptr, zx1, ML, DPROJ, HDIM);

        // conv + silu
        conv_kernel<<<gConv, TPB>>>(zx0, m_cw + (size_t)(i * 2 + 0) * CONVD * 4,
                                    m_cb + (size_t)(i * 2 + 0) * CONVD, xc0);
        conv_kernel<<<gConv, TPB>>>(zx1, m_cw + (size_t)(i * 2 + 1) * CONVD * 4,
                                    m_cb + (size_t)(i * 2 + 1) * CONVD, xc1);

        // dt / dA
        dt_kernel<<<gDt, TPB>>>(zx0, m_dtb + (i * 2 + 0) * NHEADS,
                                m_Alog + (i * 2 + 0) * NHEADS, dt0, dA0);
        dt_kernel<<<gDt, TPB>>>(zx1, m_dtb + (i * 2 + 1) * NHEADS,
                                m_Alog + (i * 2 + 1) * NHEADS, dt1, dA1);

        // sequential scan, both directions concurrently (256 blocks)
        scan_kernel<<<dim3(BATCH * NHEADS, 2), 64>>>(
            xc0, xc1, zx0, zx1, dt0, dt1, dA0, dA1, m_D + i * 2 * NHEADS, y0, y1);

        // RMSNorm (in place)
        rmsnorm_kernel<<<ML, 256>>>(y0, m_norm + (size_t)(i * 2 + 0) * DINNER);
        rmsnorm_kernel<<<ML, 256>>>(y1, m_norm + (size_t)(i * 2 + 1) * DINNER);

        // out-projections
        sgemm_nt<<<dim3((HDIM + 63) / 64, ML / 128), 256>>>(
            y0, m_Wout + (size_t)(i * 2 + 0) * HDIM * DINNER, nullptr, dr0, ML, HDIM, DINNER);
        sgemm_nt<<<dim3((HDIM + 63) / 64, ML / 128), 256>>>(
            y1, m_Wout + (size_t)(i * 2 + 1) * HDIM * DINNER, nullptr, dr1, ML, HDIM, DINNER);

        // comb = [fwd | flip(bwd)]  -> block output projection -> residual + LN
        combine_kernel<<<gEl, TPB>>>(dr0, dr1, lens, cb);
        sgemm_nt<<<dim3((HDIM + 63) / 64, ML / 128), 256>>>(
            cb, blk_Wo + (size_t)i * HDIM * DINNER, blk_bo + i * HDIM, ot, ML, HDIM, DINNER);
        addln_kernel<<<ML, 128>>>(ot, h, ln_g + i * HDIM, ln_b + i * HDIM);
    }

    // encoder_outputs = h @ W_enc^T + b_enc   (written straight into d_out)
    sgemm_nt<<<dim3((2 * HDIM + 63) / 64, ML / 128), 256>>>(
        h, W_enc, b_enc, outp, ML, 2 * HDIM, HDIM);

    // pooled mean over valid timesteps, then adapter -> encoder_hidden
    pool_kernel<<<(BATCH * 2 * HDIM) / TPB, TPB>>>(outp, lens, pl);
    adapter_kernel<<<(BATCH * HDIM) / TPB, TPB>>>(pl, W_ad, b_ad,
                                                  outp + (size_t)ML * 2 * HDIM);
}

// round 2
// speedup vs baseline: 1.7615x; 1.7615x over previous
#include <cuda_runtime.h>
#include <cuda_bf16.h>
#include <math.h>

// ---------------- problem constants ----------------
#define BATCH   8
#define SEQ     2048
#define HDIM    512
#define DPROJ   2192
#define DINNER  1024
#define DSTATE  64
#define NHEADS  16
#define HEADD   64
#define CONVD   1152
#define ML      (BATCH*SEQ)
#define EPSLN   1e-5f

typedef unsigned long long u64;

// ---------------- device scratch ----------------
__device__ float g_x0 [ML*HDIM];
__device__ float g_h  [ML*HDIM];
__device__ float g_hf [ML*HDIM];
__device__ float g_zx0[ML*DPROJ];
__device__ float g_zx1[ML*DPROJ];
__device__ float g_xc0[ML*CONVD];
__device__ float g_xc1[ML*CONVD];
__device__ float g_dt0[ML*NHEADS];
__device__ float g_dt1[ML*NHEADS];
__device__ float g_dA0[ML*NHEADS];
__device__ float g_dA1[ML*NHEADS];
__device__ float g_y0 [ML*DINNER];
__device__ float g_y1 [ML*DINNER];
__device__ float g_d0 [ML*HDIM];
__device__ float g_d1 [ML*HDIM];
__device__ float g_cb [ML*DINNER];
__device__ float g_ot [ML*HDIM];
__device__ float g_pl [BATCH*2*HDIM];

// ---------------- helpers ----------------
__device__ __forceinline__ unsigned int f2tf32(float v)
{
    unsigned int u;
    asm("cvt.rna.tf32.f32 %0, %1;" : "=r"(u) : "f"(v));
    return u;
}

__device__ __forceinline__ void mma_tf32(float c[4],
                                         unsigned a0, unsigned a1, unsigned a2, unsigned a3,
                                         unsigned b0, unsigned b1)
{
    asm volatile(
        "mma.sync.aligned.m16n8k8.row.col.f32.tf32.tf32.f32 "
        "{%0,%1,%2,%3}, {%4,%5,%6,%7}, {%8,%9}, {%0,%1,%2,%3};"
        : "+f"(c[0]), "+f"(c[1]), "+f"(c[2]), "+f"(c[3])
        : "r"(a0), "r"(a1), "r"(a2), "r"(a3), "r"(b0), "r"(b1));
}

__device__ __forceinline__ u64 fma2(u64 a, u64 b, u64 c)
{
    u64 d; asm("fma.rn.f32x2 %0,%1,%2,%3;" : "=l"(d) : "l"(a), "l"(b), "l"(c)); return d;
}
__device__ __forceinline__ u64 mul2(u64 a, u64 b)
{
    u64 d; asm("mul.rn.f32x2 %0,%1,%2;" : "=l"(d) : "l"(a), "l"(b)); return d;
}
__device__ __forceinline__ u64 add2(u64 a, u64 b)
{
    u64 d; asm("add.rn.f32x2 %0,%1,%2;" : "=l"(d) : "l"(a), "l"(b)); return d;
}
__device__ __forceinline__ u64 pack2(float lo, float hi)
{
    u64 d; asm("mov.b64 %0,{%1,%2};" : "=l"(d) : "f"(lo), "f"(hi)); return d;
}
__device__ __forceinline__ float2 unpack2(u64 v)
{
    float2 r; asm("mov.b64 {%0,%1},%2;" : "=f"(r.x), "=f"(r.y) : "l"(v)); return r;
}

// ---------------- tf32 tensor-core GEMM: C = A(MxK) @ W(NxK)^T + bias ------
// block tile 128x128, 8 warps (4 M x 2 N), warp 32x64, BK=32.
// smem [row][k] stride 36 (pad 4): conflict-free frag LDS + STS.128.
#define GST 36
__global__ __launch_bounds__(256) void tf32gemm(
    const float* __restrict__ A, const float* __restrict__ W,
    const float* __restrict__ bias, float* __restrict__ C,
    int M, int N, int K)
{
    __shared__ __align__(16) unsigned int As[128 * GST];
    __shared__ __align__(16) unsigned int Ws[128 * GST];

    const int tid  = threadIdx.x;
    const int lane = tid & 31;
    const int wid  = tid >> 5;
    const int wm   = (wid & 3) * 32;
    const int wn   = (wid >> 2) * 64;
    const int bm   = blockIdx.y * 128;
    const int bn   = blockIdx.x * 128;

    const int cm0 = tid >> 3;       // copy row base (0..31), +32 per q
    const int ckq = tid & 7;        // k-quad (0..7)

    const int fr = lane >> 2;       // fragment row 0..7
    const int fc = lane & 3;        // fragment k   0..3

    float acc[2][8][4];
#pragma unroll
    for (int i = 0; i < 2; i++)
#pragma unroll
        for (int j = 0; j < 8; j++)
#pragma unroll
            for (int r = 0; r < 4; r++) acc[i][j][r] = 0.f;

    const int nk = K >> 5;
    float4 ar[4], wr[4];
    bool wvalid[4];
#pragma unroll
    for (int q = 0; q < 4; q++) wvalid[q] = (bn + cm0 + 32 * q) < N;

    // ---- tile load (global -> regs) ----
    auto LOAD = [&](int t) {
        const float* Ap = A + (size_t)(bm + cm0) * K + t * 32 + ckq * 4;
        const float* Wp = W + (size_t)(bn + cm0) * K + t * 32 + ckq * 4;
#pragma unroll
        for (int q = 0; q < 4; q++) {
            ar[q] = *(const float4*)(Ap + (size_t)(32 * q) * K);
            wr[q] = wvalid[q] ? *(const float4*)(Wp + (size_t)(32 * q) * K)
                              : make_float4(0.f, 0.f, 0.f, 0.f);
        }
    };
    // ---- regs -> smem (cvt + STS.128) ----
    auto STORE = [&]() {
#pragma unroll
        for (int q = 0; q < 4; q++) {
            uint4 av = make_uint4(f2tf32(ar[q].x), f2tf32(ar[q].y), f2tf32(ar[q].z), f2tf32(ar[q].w));
            uint4 wv = make_uint4(f2tf32(wr[q].x), f2tf32(wr[q].y), f2tf32(wr[q].z), f2tf32(wr[q].w));
            *(uint4*)&As[(cm0 + 32 * q) * GST + ckq * 4] = av;
            *(uint4*)&Ws[(cm0 + 32 * q) * GST + ckq * 4] = wv;
        }
    };

    LOAD(0);
    STORE();
    __syncthreads();

    for (int t = 0; t < nk; t++) {
        if (t + 1 < nk) LOAD(t + 1);
#pragma unroll
        for (int ks = 0; ks < 4; ks++) {
            const int kk = ks * 8 + fc;
            unsigned b0[8], b1[8];
#pragma unroll
            for (int nf = 0; nf < 8; nf++) {
                int nrow = wn + nf * 8 + fr;
                b0[nf] = Ws[nrow * GST + kk];
                b1[nf] = Ws[nrow * GST + kk + 4];
            }
#pragma unroll
            for (int mf = 0; mf < 2; mf++) {
                int mrow = wm + mf * 16 + fr;
                unsigned a0 = As[mrow * GST + kk];
                unsigned a1 = As[(mrow + 8) * GST + kk];
                unsigned a2 = As[mrow * GST + kk + 4];
                unsigned a3 = As[(mrow + 8) * GST + kk + 4];
#pragma unroll
                for (int nf = 0; nf < 8; nf++)
                    mma_tf32(acc[mf][nf], a0, a1, a2, a3, b0[nf], b1[nf]);
            }
        }
        __syncthreads();
        if (t + 1 < nk) STORE();
        __syncthreads();
    }

    // ---- epilogue ----
#pragma unroll
    for (int mf = 0; mf < 2; mf++) {
        int r0 = bm + wm + mf * 16 + fr;
#pragma unroll
        for (int nf = 0; nf < 8; nf++) {
            int cc = bn + wn + nf * 8 + 2 * fc;
            if (cc < N) {
                float bz0 = bias ? bias[cc] : 0.f;
                float bz1 = bias ? bias[cc + 1] : 0.f;
                float2 v0 = make_float2(acc[mf][nf][0] + bz0, acc[mf][nf][1] + bz1);
                float2 v1 = make_float2(acc[mf][nf][2] + bz0, acc[mf][nf][3] + bz1);
                *(float2*)&C[(size_t)r0 * N + cc] = v0;
                *(float2*)&C[(size_t)(r0 + 8) * N + cc] = v1;
            }
        }
    }
}

// ---------------- embedding gather ----------------
__global__ void gather_embed(const int* __restrict__ tok,
                             const float* __restrict__ emb,
                             float* __restrict__ x0)
{
    int x = blockIdx.x * 256 + threadIdx.x;
    int c = x & 511;
    int m = x >> 9;
    x0[x] = emb[(size_t)tok[m] * HDIM + c];
}

// ---------------- flip ----------------
__global__ void flip_kernel(const float* __restrict__ src, float* __restrict__ dst,
                            const int* __restrict__ lens)
{
    int x = blockIdx.x * 256 + threadIdx.x;
    int c = x & 511;
    int bl = x >> 9;
    int t = bl & (SEQ - 1);
    int b = bl >> 11;
    int len = lens[b];
    int tt = (t < len) ? (len - 1 - t) : t;
    dst[x] = src[((size_t)(b * SEQ + tt) << 9) + c];
}

// ---------------- depthwise conv (k=4), 4 timesteps per thread ------------
__global__ void conv_kernel(const float* __restrict__ zx, const float* __restrict__ w,
                            const float* __restrict__ bias, float* __restrict__ xc)
{
    int x = blockIdx.x * 256 + threadIdx.x;       // (ML/4)*CONVD
    int c = x % CONVD;
    int r = x / CONVD;
    int tq = r & (SEQ / 4 - 1);
    int b  = r / (SEQ / 4);
    int t0 = tq * 4;
    const float* base = zx + ((size_t)(b * SEQ + t0)) * DPROJ + DINNER + c;
    float w0 = w[c*4], w1 = w[c*4+1], w2 = w[c*4+2], w3 = w[c*4+3], bs = bias[c];
    float v[7];
#pragma unroll
    for (int j = 0; j < 7; j++) {
        int tau = t0 - 3 + j;
        v[j] = (tau >= 0) ? base[(long)(j - 3) * DPROJ] : 0.f;
    }
#pragma unroll
    for (int tt = 0; tt < 4; tt++) {
        float a = bs + w0 * v[tt] + w1 * v[tt+1] + w2 * v[tt+2] + w3 * v[tt+3];
        xc[((size_t)(b * SEQ + t0 + tt)) * CONVD + c] = a / (1.f + __expf(-a));
    }
}

// ---------------- dt / dA ----------------
__global__ void dt_kernel(const float* __restrict__ zx, const float* __restrict__ dtb,
                          const float* __restrict__ Alog,
                          float* __restrict__ dto, float* __restrict__ dAo)
{
    int x = blockIdx.x * 256 + threadIdx.x;
    int h = x & 15;
    int bl = x >> 4;
    float v = zx[(size_t)bl * DPROJ + (DINNER + CONVD) + h] + dtb[h];
    float dt = (v > 20.f) ? v : log1pf(__expf(v));
    dto[x] = dt;
    dAo[x] = __expf(-__expf(Alog[h]) * dt);
}

// ---------------- SSM scan: f32x2 packed, prefetch, double-buffered -------
__global__ __launch_bounds__(64) void scan_kernel(
    const float* __restrict__ xc0, const float* __restrict__ xc1,
    const float* __restrict__ zx0, const float* __restrict__ zx1,
    const float* __restrict__ dtp0, const float* __restrict__ dtp1,
    const float* __restrict__ dAp0, const float* __restrict__ dAp1,
    const float* __restrict__ Dp,
    float* __restrict__ y0, float* __restrict__ y1)
{
    const int d = blockIdx.y;
    const float* xc  = d ? xc1 : xc0;
    const float* zx  = d ? zx1 : zx0;
    const float* dtp = d ? dtp1 : dtp0;
    const float* dAp = d ? dAp1 : dAp0;
    float* y = d ? y1 : y0;

    const int bh = blockIdx.x;
    const int b = bh >> 4;
    const int h = bh & 15;
    const int p = threadIdx.x;
    const float Dv = Dp[d * NHEADS + h];

    u64 s2[32];
#pragma unroll
    for (int n = 0; n < 32; n++) s2[n] = 0ull;

    __shared__ __align__(16) float Bs[2][64];
    __shared__ __align__(16) float Cs[2][64];

    const size_t rowxc = (size_t)b * SEQ * CONVD;
    const size_t rowzx = (size_t)b * SEQ * DPROJ;

    // prologue: t=0
    float Bv, Cv, xv, zv, dtv, dAv;
    {
        Bv  = xc[rowxc + DINNER + p];
        Cv  = xc[rowxc + DINNER + DSTATE + p];
        xv  = xc[rowxc + h * HEADD + p];
        zv  = zx[rowzx + h * HEADD + p];
        int bt = (b * SEQ) * NHEADS + h;
        dtv = dtp[bt];
        dAv = dAp[bt];
        Bs[0][p] = Bv; Cs[0][p] = Cv;
    }
    __syncthreads();

    for (int t = 0; t < SEQ; t++) {
        const int cur = t & 1, nxt = cur ^ 1;
        float Bn = 0.f, Cn = 0.f, xn = 0.f, zn = 0.f, dtn = 0.f, dAn = 0.f;
        if (t + 1 < SEQ) {
            size_t oc = rowxc + (size_t)(t + 1) * CONVD;
            Bn = xc[oc + DINNER + p];
            Cn = xc[oc + DINNER + DSTATE + p];
            xn = xc[oc + h * HEADD + p];
            zn = zx[rowzx + (size_t)(t + 1) * DPROJ + h * HEADD + p];
            int bt = (b * SEQ + t + 1) * NHEADS + h;
            dtn = dtp[bt];
            dAn = dAp[bt];
        }

        float kf = dtv * xv;
        u64 dA2 = pack2(dAv, dAv);
        u64 k2  = pack2(kf, kf);
        u64 aA = 0ull, aB = 0ull;
        const double2* Bp = (const double2*)&Bs[cur][0];
        const double2* Cp = (const double2*)&Cs[cur][0];
#pragma unroll
        for (int i = 0; i < 16; i++) {
            double2 bb = Bp[i], cc2 = Cp[i];
            u64 blo = __double_as_longlong(bb.x),  bhi = __double_as_longlong(bb.y);
            u64 clo = __double_as_longlong(cc2.x), chi = __double_as_longlong(cc2.y);
            s2[2*i]   = fma2(s2[2*i],   dA2, mul2(k2, blo));
            s2[2*i+1] = fma2(s2[2*i+1], dA2, mul2(k2, bhi));
            aA = fma2(s2[2*i],   clo, aA);
            aB = fma2(s2[2*i+1], chi, aB);
        }
        float2 av = unpack2(add2(aA, aB));
        float yv = av.x + av.y + Dv * xv;
        float sg = zv / (1.f + __expf(-zv));
        y[(size_t)(b * SEQ + t) * DINNER + h * HEADD + p] = yv * sg;

        Bs[nxt][p] = Bn; Cs[nxt][p] = Cn;
        __syncthreads();
        Bv = Bn; Cv = Cn; xv = xn; zv = zn; dtv = dtn; dAv = dAn;
    }
}

// ---------------- RMSNorm ----------------
__global__ __launch_bounds__(256) void rmsnorm_kernel(float* __restrict__ y,
                                                      const float* __restrict__ w)
{
    int row = blockIdx.x;
    float* p = y + (size_t)row * DINNER;
    int tid = threadIdx.x;
    float v[4];
    float ss = 0.f;
#pragma unroll
    for (int i = 0; i < 4; i++) { v[i] = p[tid + i * 256]; ss += v[i] * v[i]; }
#pragma unroll
    for (int o = 16; o; o >>= 1) ss += __shfl_xor_sync(0xffffffffu, ss, o);
    __shared__ float red[8];
    if ((tid & 31) == 0) red[tid >> 5] = ss;
    __syncthreads();
    float tot = 0.f;
#pragma unroll
    for (int i = 0; i < 8; i++) tot += red[i];
    float sc = rsqrtf(tot * (1.f / DINNER) + EPSLN);
#pragma unroll
    for (int i = 0; i < 4; i++)
        p[tid + i * 256] = v[i] * sc * w[tid + i * 256];
}

// ---------------- combine ----------------
__global__ void combine_kernel(const float* __restrict__ fwd, const float* __restrict__ bwd,
                               const int* __restrict__ lens, float* __restrict__ comb)
{
    int x = blockIdx.x * 256 + threadIdx.x;
    int c = x & 511;
    int bl = x >> 9;
    int t = bl & (SEQ - 1);
    int b = bl >> 11;
    comb[(size_t)bl * DINNER + c] = fwd[(size_t)bl * HDIM + c];
    int len = lens[b];
    int tt = (t < len) ? (len - 1 - t) : t;
    comb[(size_t)bl * DINNER + HDIM + c] = bwd[((size_t)(b * SEQ + tt)) * HDIM + c];
}

// ---------------- add + layernorm ----------------
__global__ __launch_bounds__(128) void addln_kernel(const float* __restrict__ out,
                                                    float* __restrict__ h,
                                                    const float* __restrict__ g,
                                                    const float* __restrict__ bta)
{
    int row = blockIdx.x;
    const float* po = out + (size_t)row * HDIM;
    float* ph = h + (size_t)row * HDIM;
    int tid = threadIdx.x;
    float v[4];
    float sum = 0.f;
#pragma unroll
    for (int i = 0; i < 4; i++) { v[i] = po[tid + i * 128] + ph[tid + i * 128]; sum += v[i]; }
#pragma unroll
    for (int o = 16; o; o >>= 1) sum += __shfl_xor_sync(0xffffffffu, sum, o);
    __shared__ float red[4];
    if ((tid & 31) == 0) red[tid >> 5] = sum;
    __syncthreads();
    float mean = (red[0] + red[1] + red[2] + red[3]) * (1.f / HDIM);
    float vs = 0.f;
#pragma unroll
    for (int i = 0; i < 4; i++) { float dd = v[i] - mean; vs += dd * dd; }
#pragma unroll
    for (int o = 16; o; o >>= 1) vs += __shfl_xor_sync(0xffffffffu, vs, o);
    __syncthreads();
    if ((tid & 31) == 0) red[tid >> 5] = vs;
    __syncthreads();
    float var = (red[0] + red[1] + red[2] + red[3]) * (1.f / HDIM);
    float sc = rsqrtf(var + EPSLN);
#pragma unroll
    for (int i = 0; i < 4; i++) {
        int c = tid + i * 128;
        ph[c] = (v[i] - mean) * sc * g[c] + bta[c];
    }
}

// ---------------- masked mean pool (coalesced) ----------------
__global__ __launch_bounds__(256) void pool_kernel(const float* __restrict__ enc,
                                                   const int* __restrict__ lens,
                                                   float* __restrict__ pooled)
{
    int b  = blockIdx.x >> 5;
    int c0 = (blockIdx.x & 31) * 32;
    int c  = threadIdx.x & 31;
    int ts = threadIdx.x >> 5;
    int len = lens[b];
    float s = 0.f;
    for (int t = ts; t < len; t += 8)
        s += enc[((size_t)(b * SEQ + t)) * (2 * HDIM) + c0 + c];
    __shared__ float red[8][32];
    red[ts][c] = s;
    __syncthreads();
    if (ts == 0) {
        float tot = 0.f;
#pragma unroll
        for (int i = 0; i < 8; i++) tot += red[i][c];
        pooled[b * (2 * HDIM) + c0 + c] = tot / (float)(len > 0 ? len : 1);
    }
}

// ---------------- adapter (warp per output) ----------------
__global__ __launch_bounds__(256) void adapter_kernel(const float* __restrict__ pooled,
                                                      const float* __restrict__ Wad,
                                                      const float* __restrict__ bad,
                                                      float* __restrict__ out)
{
    int w = blockIdx.x * 8 + (threadIdx.x >> 5);
    int lane = threadIdx.x & 31;
    int o = w & 511, b = w >> 9;
    const float* pr = pooled + (size_t)b * (2 * HDIM);
    const float* wr = Wad + (size_t)o * (2 * HDIM);
    float s = 0.f;
    for (int i = lane; i < 2 * HDIM; i += 32) s += pr[i] * wr[i];
#pragma unroll
    for (int off = 16; off; off >>= 1) s += __shfl_xor_sync(0xffffffffu, s, off);
    if (lane == 0) out[b * HDIM + o] = tanhf(s + bad[o]);
}

// ---------------- host ----------------
static float* symaddr(const void* s)
{
    void* p = nullptr;
    cudaGetSymbolAddress(&p, s);
    return (float*)p;
}

static inline dim3 ggrid(int N) { return dim3((N + 127) / 128, ML / 128); }

extern "C" void kernel_launch(void* const* d_in, const int* in_sizes, int n_in,
                              void* d_out, int out_size)
{
    const int*   tok    = (const int*)  d_in[0];
    const int*   lens   = (const int*)  d_in[1];
    const float* emb    = (const float*)d_in[2];
    const float* W_inp  = (const float*)d_in[3];
    const float* b_inp  = (const float*)d_in[4];
    const float* m_Win  = (const float*)d_in[5];
    const float* m_cw   = (const float*)d_in[6];
    const float* m_cb   = (const float*)d_in[7];
    const float* m_dtb  = (const float*)d_in[8];
    const float* m_Alog = (const float*)d_in[9];
    const float* m_D    = (const float*)d_in[10];
    const float* m_norm = (const float*)d_in[11];
    const float* m_Wout = (const float*)d_in[12];
    const float* blk_Wo = (const float*)d_in[13];
    const float* blk_bo = (const float*)d_in[14];
    const float* ln_g   = (const float*)d_in[15];
    const float* ln_b   = (const float*)d_in[16];
    const float* W_enc  = (const float*)d_in[17];
    const float* b_enc  = (const float*)d_in[18];
    const float* W_ad   = (const float*)d_in[19];
    const float* b_ad   = (const float*)d_in[20];
    float* outp = (float*)d_out;

    float* x0  = symaddr(g_x0);
    float* h   = symaddr(g_h);
    float* hf  = symaddr(g_hf);
    float* zx0 = symaddr(g_zx0);
    float* zx1 = symaddr(g_zx1);
    float* xc0 = symaddr(g_xc0);
    float* xc1 = symaddr(g_xc1);
    float* dt0 = symaddr(g_dt0);
    float* dt1 = symaddr(g_dt1);
    float* dA0 = symaddr(g_dA0);
    float* dA1 = symaddr(g_dA1);
    float* y0  = symaddr(g_y0);
    float* y1  = symaddr(g_y1);
    float* dr0 = symaddr(g_d0);
    float* dr1 = symaddr(g_d1);
    float* cb  = symaddr(g_cb);
    float* ot  = symaddr(g_ot);
    float* pl  = symaddr(g_pl);

    const int TPB = 256;
    dim3 gEl(ML * HDIM / TPB);
    dim3 gConv((ML / 4) * CONVD / TPB);
    dim3 gDt((ML * NHEADS) / TPB);

    gather_embed<<<gEl, TPB>>>(tok, emb, x0);
    tf32gemm<<<ggrid(HDIM), 256>>>(x0, W_inp, b_inp, h, ML, HDIM, HDIM);

    for (int i = 0; i < 4; i++) {
        flip_kernel<<<gEl, TPB>>>(h, hf, lens);

        tf32gemm<<<ggrid(DPROJ), 256>>>(
            h,  m_Win + (size_t)(i * 2 + 0) * DPROJ * HDIM, nullptr, zx0, ML, DPROJ, HDIM);
        tf32gemm<<<ggrid(DPROJ), 256>>>(
            hf, m_Win + (size_t)(i * 2 + 1) * DPROJ * HDIM, nullptr, zx1, ML, DPROJ, HDIM);

        conv_kernel<<<gConv, TPB>>>(zx0, m_cw + (size_t)(i * 2 + 0) * CONVD * 4,
                                    m_cb + (size_t)(i * 2 + 0) * CONVD, xc0);
        conv_kernel<<<gConv, TPB>>>(zx1, m_cw + (size_t)(i * 2 + 1) * CONVD * 4,
                                    m_cb + (size_t)(i * 2 + 1) * CONVD, xc1);

        dt_kernel<<<gDt, TPB>>>(zx0, m_dtb + (i * 2 + 0) * NHEADS,
                                m_Alog + (i * 2 + 0) * NHEADS, dt0, dA0);
        dt_kernel<<<gDt, TPB>>>(zx1, m_dtb + (i * 2 + 1) * NHEADS,
                                m_Alog + (i * 2 + 1) * NHEADS, dt1, dA1);

        scan_kernel<<<dim3(BATCH * NHEADS, 2), 64>>>(
            xc0, xc1, zx0, zx1, dt0, dt1, dA0, dA1, m_D + i * 2 * NHEADS, y0, y1);

        rmsnorm_kernel<<<ML, 256>>>(y0, m_norm + (size_t)(i * 2 + 0) * DINNER);
        rmsnorm_kernel<<<ML, 256>>>(y1, m_norm + (size_t)(i * 2 + 1) * DINNER);

        tf32gemm<<<ggrid(HDIM), 256>>>(
            y0, m_Wout + (size_t)(i * 2 + 0) * HDIM * DINNER, nullptr, dr0, ML, HDIM, DINNER);
        tf32gemm<<<ggrid(HDIM), 256>>>(
            y1, m_Wout + (size_t)(i * 2 + 1) * HDIM * DINNER, nullptr, dr1, ML, HDIM, DINNER);

        combine_kernel<<<gEl, TPB>>>(dr0, dr1, lens, cb);
        tf32gemm<<<ggrid(HDIM), 256>>>(
            cb, blk_Wo + (size_t)i * HDIM * DINNER, blk_bo + i * HDIM, ot, ML, HDIM, DINNER);
        addln_kernel<<<ML, 128>>>(ot, h, ln_g + i * HDIM, ln_b + i * HDIM);
    }

    tf32gemm<<<ggrid(2 * HDIM), 256>>>(h, W_enc, b_enc, outp, ML, 2 * HDIM, HDIM);

    pool_kernel<<<BATCH * 32, 256>>>(outp, lens, pl);
    adapter_kernel<<<(BATCH * HDIM) / 8, 256>>>(pl, W_ad, b_ad,
                                                outp + (size_t)ML * 2 * HDIM);
}

// round 3
// speedup vs baseline: 2.0315x; 1.1532x over previous
#include <cuda_runtime.h>
#include <cuda_bf16.h>
#include <math.h>

// ---------------- problem constants ----------------
#define BATCH   8
#define SEQ     2048
#define HDIM    512
#define DPROJ   2192
#define DINNER  1024
#define DSTATE  64
#define NHEADS  16
#define HEADD   64
#define CONVD   1152
#define ML      (BATCH*SEQ)
#define EPSLN   1e-5f

typedef unsigned long long u64;

// ---------------- device scratch ----------------
__device__ float g_x0 [ML*HDIM];
__device__ float g_h  [ML*HDIM];
__device__ float g_hf [ML*HDIM];
__device__ float g_zx0[ML*DPROJ];
__device__ float g_zx1[ML*DPROJ];
__device__ float g_xc0[ML*CONVD];
__device__ float g_xc1[ML*CONVD];
__device__ float g_dt0[ML*NHEADS];
__device__ float g_dt1[ML*NHEADS];
__device__ float g_dA0[ML*NHEADS];
__device__ float g_dA1[ML*NHEADS];
__device__ float g_y0 [ML*DINNER];
__device__ float g_y1 [ML*DINNER];
__device__ float g_d1 [ML*HDIM];
__device__ float g_cb [ML*DINNER];
__device__ float g_ot [ML*HDIM];
__device__ float g_pl [BATCH*2*HDIM];

// ---------------- helpers ----------------
__device__ __forceinline__ unsigned int f2tf32(float v)
{
    unsigned int u;
    asm("cvt.rna.tf32.f32 %0, %1;" : "=r"(u) : "f"(v));
    return u;
}

__device__ __forceinline__ void mma_tf32(float c[4],
                                         unsigned a0, unsigned a1, unsigned a2, unsigned a3,
                                         unsigned b0, unsigned b1)
{
    asm volatile(
        "mma.sync.aligned.m16n8k8.row.col.f32.tf32.tf32.f32 "
        "{%0,%1,%2,%3}, {%4,%5,%6,%7}, {%8,%9}, {%0,%1,%2,%3};"
        : "+f"(c[0]), "+f"(c[1]), "+f"(c[2]), "+f"(c[3])
        : "r"(a0), "r"(a1), "r"(a2), "r"(a3), "r"(b0), "r"(b1));
}

__device__ __forceinline__ u64 fma2(u64 a, u64 b, u64 c)
{
    u64 d; asm("fma.rn.f32x2 %0,%1,%2,%3;" : "=l"(d) : "l"(a), "l"(b), "l"(c)); return d;
}
__device__ __forceinline__ u64 mul2(u64 a, u64 b)
{
    u64 d; asm("mul.rn.f32x2 %0,%1,%2;" : "=l"(d) : "l"(a), "l"(b)); return d;
}
__device__ __forceinline__ u64 add2(u64 a, u64 b)
{
    u64 d; asm("add.rn.f32x2 %0,%1,%2;" : "=l"(d) : "l"(a), "l"(b)); return d;
}
__device__ __forceinline__ u64 pack2(float lo, float hi)
{
    u64 d; asm("mov.b64 %0,{%1,%2};" : "=l"(d) : "f"(lo), "f"(hi)); return d;
}
__device__ __forceinline__ float2 unpack2(u64 v)
{
    float2 r; asm("mov.b64 {%0,%1},%2;" : "=f"(r.x), "=f"(r.y) : "l"(v)); return r;
}

// ---------------- tf32 tensor-core GEMM, double-buffered, 1 sync/tile -----
// C[m, cofs+n] = sum_k A[m,k]*W[n,k] (+bias[n]);  C row stride = ldc.
#define GST 36
#define GSZ (128*GST)           // words per (As or Ws) buffer
#define GEMM_SMEM (4*GSZ*4)     // bytes: 2 buffers x (As+Ws)

__global__ __launch_bounds__(256) void tf32gemm(
    const float* __restrict__ A, const float* __restrict__ W,
    const float* __restrict__ bias, float* __restrict__ C,
    int M, int N, int K, int ldc)
{
    extern __shared__ __align__(16) unsigned int dsm[];

    const int tid  = threadIdx.x;
    const int lane = tid & 31;
    const int wid  = tid >> 5;
    const int wm   = (wid & 3) * 32;
    const int wn   = (wid >> 2) * 64;
    const int bm   = blockIdx.y * 128;
    const int bn   = blockIdx.x * 128;

    const int cm0 = tid >> 3;       // copy row base (0..31), +32 per q
    const int ckq = tid & 7;        // k-quad

    const int fr = lane >> 2;       // fragment row 0..7
    const int fc = lane & 3;        // fragment k   0..3

    float acc[2][8][4];
#pragma unroll
    for (int i = 0; i < 2; i++)
#pragma unroll
        for (int j = 0; j < 8; j++)
#pragma unroll
            for (int r = 0; r < 4; r++) acc[i][j][r] = 0.f;

    const int nk = K >> 5;
    float4 ar[4], wr[4];
    bool wvalid[4];
#pragma unroll
    for (int q = 0; q < 4; q++) wvalid[q] = (bn + cm0 + 32 * q) < N;

    const float* Abase = A + (size_t)(bm + cm0) * K + ckq * 4;
    const float* Wbase = W + (size_t)(bn + cm0) * K + ckq * 4;

    auto LOAD = [&](int t) {
        const float* Ap = Abase + t * 32;
        const float* Wp = Wbase + t * 32;
#pragma unroll
        for (int q = 0; q < 4; q++) {
            ar[q] = *(const float4*)(Ap + (size_t)(32 * q) * K);
            wr[q] = wvalid[q] ? *(const float4*)(Wp + (size_t)(32 * q) * K)
                              : make_float4(0.f, 0.f, 0.f, 0.f);
        }
    };
    auto STORE = [&](int buf) {
        unsigned int* Asb = dsm + buf * 2 * GSZ;
        unsigned int* Wsb = Asb + GSZ;
#pragma unroll
        for (int q = 0; q < 4; q++) {
            uint4 av = make_uint4(f2tf32(ar[q].x), f2tf32(ar[q].y), f2tf32(ar[q].z), f2tf32(ar[q].w));
            uint4 wv = make_uint4(f2tf32(wr[q].x), f2tf32(wr[q].y), f2tf32(wr[q].z), f2tf32(wr[q].w));
            *(uint4*)&Asb[(cm0 + 32 * q) * GST + ckq * 4] = av;
            *(uint4*)&Wsb[(cm0 + 32 * q) * GST + ckq * 4] = wv;
        }
    };

    LOAD(0);
    STORE(0);
    __syncthreads();

    for (int t = 0; t < nk; t++) {
        const int cur = t & 1;
        if (t + 1 < nk) LOAD(t + 1);

        const unsigned int* Ac = dsm + cur * 2 * GSZ;
        const unsigned int* Wc = Ac + GSZ;
#pragma unroll
        for (int ks = 0; ks < 4; ks++) {
            const int kk = ks * 8 + fc;
            unsigned b0[8], b1[8];
#pragma unroll
            for (int nf = 0; nf < 8; nf++) {
                int nrow = wn + nf * 8 + fr;
                b0[nf] = Wc[nrow * GST + kk];
                b1[nf] = Wc[nrow * GST + kk + 4];
            }
#pragma unroll
            for (int mf = 0; mf < 2; mf++) {
                int mrow = wm + mf * 16 + fr;
                unsigned a0 = Ac[mrow * GST + kk];
                unsigned a1 = Ac[(mrow + 8) * GST + kk];
                unsigned a2 = Ac[mrow * GST + kk + 4];
                unsigned a3 = Ac[(mrow + 8) * GST + kk + 4];
#pragma unroll
                for (int nf = 0; nf < 8; nf++)
                    mma_tf32(acc[mf][nf], a0, a1, a2, a3, b0[nf], b1[nf]);
            }
        }
        if (t + 1 < nk) STORE(cur ^ 1);
        __syncthreads();
    }

#pragma unroll
    for (int mf = 0; mf < 2; mf++) {
        int r0 = bm + wm + mf * 16 + fr;
#pragma unroll
        for (int nf = 0; nf < 8; nf++) {
            int cc = bn + wn + nf * 8 + 2 * fc;
            if (cc < N) {
                float bz0 = bias ? bias[cc] : 0.f;
                float bz1 = bias ? bias[cc + 1] : 0.f;
                float2 v0 = make_float2(acc[mf][nf][0] + bz0, acc[mf][nf][1] + bz1);
                float2 v1 = make_float2(acc[mf][nf][2] + bz0, acc[mf][nf][3] + bz1);
                *(float2*)&C[(size_t)r0 * ldc + cc] = v0;
                *(float2*)&C[(size_t)(r0 + 8) * ldc + cc] = v1;
            }
        }
    }
}

// ---------------- embedding gather ----------------
__global__ void gather_embed(const int* __restrict__ tok,
                             const float* __restrict__ emb,
                             float* __restrict__ x0)
{
    int x = blockIdx.x * 256 + threadIdx.x;
    int c = x & 511;
    int m = x >> 9;
    x0[x] = emb[(size_t)tok[m] * HDIM + c];
}

// ---------------- flip ----------------
__global__ void flip_kernel(const float* __restrict__ src, float* __restrict__ dst,
                            const int* __restrict__ lens)
{
    int x = blockIdx.x * 256 + threadIdx.x;
    int c = x & 511;
    int bl = x >> 9;
    int t = bl & (SEQ - 1);
    int b = bl >> 11;
    int len = lens[b];
    int tt = (t < len) ? (len - 1 - t) : t;
    dst[x] = src[((size_t)(b * SEQ + tt) << 9) + c];
}

// ---------------- depthwise conv (k=4), 4 timesteps per thread ------------
__global__ void conv_kernel(const float* __restrict__ zx, const float* __restrict__ w,
                            const float* __restrict__ bias, float* __restrict__ xc)
{
    int x = blockIdx.x * 256 + threadIdx.x;
    int c = x % CONVD;
    int r = x / CONVD;
    int tq = r & (SEQ / 4 - 1);
    int b  = r / (SEQ / 4);
    int t0 = tq * 4;
    const float* base = zx + ((size_t)(b * SEQ + t0)) * DPROJ + DINNER + c;
    float w0 = w[c*4], w1 = w[c*4+1], w2 = w[c*4+2], w3 = w[c*4+3], bs = bias[c];
    float v[7];
#pragma unroll
    for (int j = 0; j < 7; j++) {
        int tau = t0 - 3 + j;
        v[j] = (tau >= 0) ? base[(long)(j - 3) * DPROJ] : 0.f;
    }
#pragma unroll
    for (int tt = 0; tt < 4; tt++) {
        float a = bs + w0 * v[tt] + w1 * v[tt+1] + w2 * v[tt+2] + w3 * v[tt+3];
        xc[((size_t)(b * SEQ + t0 + tt)) * CONVD + c] = a / (1.f + __expf(-a));
    }
}

// ---------------- dt / dA ----------------
__global__ void dt_kernel(const float* __restrict__ zx, const float* __restrict__ dtb,
                          const float* __restrict__ Alog,
                          float* __restrict__ dto, float* __restrict__ dAo)
{
    int x = blockIdx.x * 256 + threadIdx.x;
    int h = x & 15;
    int bl = x >> 4;
    float v = zx[(size_t)bl * DPROJ + (DINNER + CONVD) + h] + dtb[h];
    float dt = (v > 20.f) ? v : log1pf(__expf(v));
    dto[x] = dt;
    dAo[x] = __expf(-__expf(Alog[h]) * dt);
}

// ---------------- SSM scan: 256 threads/block, 16 states/thread -----------
// thread (p = tid>>2, q = tid&3) owns states n = q*16 .. q*16+15 of row p.
__global__ __launch_bounds__(256) void scan_kernel(
    const float* __restrict__ xc0, const float* __restrict__ xc1,
    const float* __restrict__ zx0, const float* __restrict__ zx1,
    const float* __restrict__ dtp0, const float* __restrict__ dtp1,
    const float* __restrict__ dAp0, const float* __restrict__ dAp1,
    const float* __restrict__ Dp,
    float* __restrict__ y0, float* __restrict__ y1)
{
    const int d = blockIdx.y;
    const float* xc  = d ? xc1 : xc0;
    const float* zx  = d ? zx1 : zx0;
    const float* dtp = d ? dtp1 : dtp0;
    const float* dAp = d ? dAp1 : dAp0;
    float* y = d ? y1 : y0;

    const int bh = blockIdx.x;
    const int b = bh >> 4;
    const int h = bh & 15;
    const int tid = threadIdx.x;
    const int p = tid >> 2;
    const int q = tid & 3;
    const float Dv = Dp[d * NHEADS + h];

    u64 s2[8];
#pragma unroll
    for (int n = 0; n < 8; n++) s2[n] = 0ull;

    __shared__ __align__(16) float Bs[2][64];
    __shared__ __align__(16) float Cs[2][64];

    const size_t rowxc = (size_t)b * SEQ * CONVD;
    const size_t rowzx = (size_t)b * SEQ * DPROJ;

    // prologue t=0
    float xv, zv, dtv, dAv, ldv = 0.f;
    {
        if (tid < 64)       ldv = xc[rowxc + DINNER + tid];
        else if (tid < 128) ldv = xc[rowxc + DINNER + DSTATE + (tid - 64)];
        if (tid < 64)       Bs[0][tid] = ldv;
        else if (tid < 128) Cs[0][tid - 64] = ldv;
        xv = xc[rowxc + h * HEADD + p];
        zv = zx[rowzx + h * HEADD + p];
        int bt = (b * SEQ) * NHEADS + h;
        dtv = dtp[bt];
        dAv = dAp[bt];
    }
    __syncthreads();

    for (int t = 0; t < SEQ; t++) {
        const int cur = t & 1, nxt = cur ^ 1;

        // prefetch t+1
        float xn = 0.f, zn = 0.f, dtn = 0.f, dAn = 0.f, ldn = 0.f;
        if (t + 1 < SEQ) {
            size_t oc = rowxc + (size_t)(t + 1) * CONVD;
            if (tid < 64)       ldn = xc[oc + DINNER + tid];
            else if (tid < 128) ldn = xc[oc + DINNER + DSTATE + (tid - 64)];
            xn = xc[oc + h * HEADD + p];
            zn = zx[rowzx + (size_t)(t + 1) * DPROJ + h * HEADD + p];
            int bt = (b * SEQ + t + 1) * NHEADS + h;
            dtn = dtp[bt];
            dAn = dAp[bt];
        }

        float kf = dtv * xv;
        u64 dA2 = pack2(dAv, dAv);
        u64 k2  = pack2(kf, kf);
        const double2* Bp = (const double2*)&Bs[cur][q * 16];
        const double2* Cp = (const double2*)&Cs[cur][q * 16];
        u64 aA = 0ull, aB = 0ull;
#pragma unroll
        for (int i = 0; i < 4; i++) {
            double2 bb = Bp[i], cc2 = Cp[i];
            u64 blo = __double_as_longlong(bb.x),  bhi = __double_as_longlong(bb.y);
            u64 clo = __double_as_longlong(cc2.x), chi = __double_as_longlong(cc2.y);
            s2[2*i]   = fma2(s2[2*i],   dA2, mul2(k2, blo));
            s2[2*i+1] = fma2(s2[2*i+1], dA2, mul2(k2, bhi));
            aA = fma2(s2[2*i],   clo, aA);
            aB = fma2(s2[2*i+1], chi, aB);
        }
        float2 av = unpack2(add2(aA, aB));
        float acc = av.x + av.y;
        acc += __shfl_xor_sync(0xffffffffu, acc, 1);
        acc += __shfl_xor_sync(0xffffffffu, acc, 2);
        if (q == 0) {
            float sg = zv / (1.f + __expf(-zv));
            y[(size_t)(b * SEQ + t) * DINNER + h * HEADD + p] = (acc + Dv * xv) * sg;
        }

        if (tid < 64)       Bs[nxt][tid] = ldn;
        else if (tid < 128) Cs[nxt][tid - 64] = ldn;
        __syncthreads();
        xv = xn; zv = zn; dtv = dtn; dAv = dAn;
    }
}

// ---------------- RMSNorm ----------------
__global__ __launch_bounds__(256) void rmsnorm_kernel(float* __restrict__ y,
                                                      const float* __restrict__ w)
{
    int row = blockIdx.x;
    float* p = y + (size_t)row * DINNER;
    int tid = threadIdx.x;
    float v[4];
    float ss = 0.f;
#pragma unroll
    for (int i = 0; i < 4; i++) { v[i] = p[tid + i * 256]; ss += v[i] * v[i]; }
#pragma unroll
    for (int o = 16; o; o >>= 1) ss += __shfl_xor_sync(0xffffffffu, ss, o);
    __shared__ float red[8];
    if ((tid & 31) == 0) red[tid >> 5] = ss;
    __syncthreads();
    float tot = 0.f;
#pragma unroll
    for (int i = 0; i < 8; i++) tot += red[i];
    float sc = rsqrtf(tot * (1.f / DINNER) + EPSLN);
#pragma unroll
    for (int i = 0; i < 4; i++)
        p[tid + i * 256] = v[i] * sc * w[tid + i * 256];
}

// ---------------- flip-cat: comb[:,512:] = flip(bwd) ----------------
__global__ void flipcat_kernel(const float* __restrict__ bwd,
                               const int* __restrict__ lens, float* __restrict__ comb)
{
    int x = blockIdx.x * 256 + threadIdx.x;
    int c = x & 511;
    int bl = x >> 9;
    int t = bl & (SEQ - 1);
    int b = bl >> 11;
    int len = lens[b];
    int tt = (t < len) ? (len - 1 - t) : t;
    comb[(size_t)bl * DINNER + HDIM + c] = bwd[((size_t)(b * SEQ + tt)) * HDIM + c];
}

// ---------------- add + layernorm ----------------
__global__ __launch_bounds__(128) void addln_kernel(const float* __restrict__ out,
                                                    float* __restrict__ h,
                                                    const float* __restrict__ g,
                                                    const float* __restrict__ bta)
{
    int row = blockIdx.x;
    const float* po = out + (size_t)row * HDIM;
    float* ph = h + (size_t)row * HDIM;
    int tid = threadIdx.x;
    float v[4];
    float sum = 0.f;
#pragma unroll
    for (int i = 0; i < 4; i++) { v[i] = po[tid + i * 128] + ph[tid + i * 128]; sum += v[i]; }
#pragma unroll
    for (int o = 16; o; o >>= 1) sum += __shfl_xor_sync(0xffffffffu, sum, o);
    __shared__ float red[4];
    if ((tid & 31) == 0) red[tid >> 5] = sum;
    __syncthreads();
    float mean = (red[0] + red[1] + red[2] + red[3]) * (1.f / HDIM);
    float vs = 0.f;
#pragma unroll
    for (int i = 0; i < 4; i++) { float dd = v[i] - mean; vs += dd * dd; }
#pragma unroll
    for (int o = 16; o; o >>= 1) vs += __shfl_xor_sync(0xffffffffu, vs, o);
    __syncthreads();
    if ((tid & 31) == 0) red[tid >> 5] = vs;
    __syncthreads();
    float var = (red[0] + red[1] + red[2] + red[3]) * (1.f / HDIM);
    float sc = rsqrtf(var + EPSLN);
#pragma unroll
    for (int i = 0; i < 4; i++) {
        int c = tid + i * 128;
        ph[c] = (v[i] - mean) * sc * g[c] + bta[c];
    }
}

// ---------------- masked mean pool ----------------
__global__ __launch_bounds__(256) void pool_kernel(const float* __restrict__ enc,
                                                   const int* __restrict__ lens,
                                                   float* __restrict__ pooled)
{
    int b  = blockIdx.x >> 5;
    int c0 = (blockIdx.x & 31) * 32;
    int c  = threadIdx.x & 31;
    int ts = threadIdx.x >> 5;
    int len = lens[b];
    float s = 0.f;
    for (int t = ts; t < len; t += 8)
        s += enc[((size_t)(b * SEQ + t)) * (2 * HDIM) + c0 + c];
    __shared__ float red[8][32];
    red[ts][c] = s;
    __syncthreads();
    if (ts == 0) {
        float tot = 0.f;
#pragma unroll
        for (int i = 0; i < 8; i++) tot += red[i][c];
        pooled[b * (2 * HDIM) + c0 + c] = tot / (float)(len > 0 ? len : 1);
    }
}

// ---------------- adapter ----------------
__global__ __launch_bounds__(256) void adapter_kernel(const float* __restrict__ pooled,
                                                      const float* __restrict__ Wad,
                                                      const float* __restrict__ bad,
                                                      float* __restrict__ out)
{
    int w = blockIdx.x * 8 + (threadIdx.x >> 5);
    int lane = threadIdx.x & 31;
    int o = w & 511, b = w >> 9;
    const float* pr = pooled + (size_t)b * (2 * HDIM);
    const float* wr = Wad + (size_t)o * (2 * HDIM);
    float s = 0.f;
    for (int i = lane; i < 2 * HDIM; i += 32) s += pr[i] * wr[i];
#pragma unroll
    for (int off = 16; off; off >>= 1) s += __shfl_xor_sync(0xffffffffu, s, off);
    if (lane == 0) out[b * HDIM + o] = tanhf(s + bad[o]);
}

// ---------------- host ----------------
static float* symaddr(const void* s)
{
    void* p = nullptr;
    cudaGetSymbolAddress(&p, s);
    return (float*)p;
}

static inline dim3 ggrid(int N) { return dim3((N + 127) / 128, ML / 128); }

extern "C" void kernel_launch(void* const* d_in, const int* in_sizes, int n_in,
                              void* d_out, int out_size)
{
    const int*   tok    = (const int*)  d_in[0];
    const int*   lens   = (const int*)  d_in[1];
    const float* emb    = (const float*)d_in[2];
    const float* W_inp  = (const float*)d_in[3];
    const float* b_inp  = (const float*)d_in[4];
    const float* m_Win  = (const float*)d_in[5];
    const float* m_cw   = (const float*)d_in[6];
    const float* m_cb   = (const float*)d_in[7];
    const float* m_dtb  = (const float*)d_in[8];
    const float* m_Alog = (const float*)d_in[9];
    const float* m_D    = (const float*)d_in[10];
    const float* m_norm = (const float*)d_in[11];
    const float* m_Wout = (const float*)d_in[12];
    const float* blk_Wo = (const float*)d_in[13];
    const float* blk_bo = (const float*)d_in[14];
    const float* ln_g   = (const float*)d_in[15];
    const float* ln_b   = (const float*)d_in[16];
    const float* W_enc  = (const float*)d_in[17];
    const float* b_enc  = (const float*)d_in[18];
    const float* W_ad   = (const float*)d_in[19];
    const float* b_ad   = (const float*)d_in[20];
    float* outp = (float*)d_out;

    float* x0  = symaddr(g_x0);
    float* h   = symaddr(g_h);
    float* hf  = symaddr(g_hf);
    float* zx0 = symaddr(g_zx0);
    float* zx1 = symaddr(g_zx1);
    float* xc0 = symaddr(g_xc0);
    float* xc1 = symaddr(g_xc1);
    float* dt0 = symaddr(g_dt0);
    float* dt1 = symaddr(g_dt1);
    float* dA0 = symaddr(g_dA0);
    float* dA1 = symaddr(g_dA1);
    float* y0  = symaddr(g_y0);
    float* y1  = symaddr(g_y1);
    float* dr1 = symaddr(g_d1);
    float* cb  = symaddr(g_cb);
    float* ot  = symaddr(g_ot);
    float* pl  = symaddr(g_pl);

    static int smem_set = 0;
    if (!smem_set) {
        cudaFuncSetAttribute(tf32gemm, cudaFuncAttributeMaxDynamicSharedMemorySize, GEMM_SMEM);
        smem_set = 1;
    }

    const int TPB = 256;
    dim3 gEl(ML * HDIM / TPB);
    dim3 gConv((ML / 4) * CONVD / TPB);
    dim3 gDt((ML * NHEADS) / TPB);

    gather_embed<<<gEl, TPB>>>(tok, emb, x0);
    tf32gemm<<<ggrid(HDIM), 256, GEMM_SMEM>>>(x0, W_inp, b_inp, h, ML, HDIM, HDIM, HDIM);

    for (int i = 0; i < 4; i++) {
        flip_kernel<<<gEl, TPB>>>(h, hf, lens);

        tf32gemm<<<ggrid(DPROJ), 256, GEMM_SMEM>>>(
            h,  m_Win + (size_t)(i * 2 + 0) * DPROJ * HDIM, nullptr, zx0, ML, DPROJ, HDIM, DPROJ);
        tf32gemm<<<ggrid(DPROJ), 256, GEMM_SMEM>>>(
            hf, m_Win + (size_t)(i * 2 + 1) * DPROJ * HDIM, nullptr, zx1, ML, DPROJ, HDIM, DPROJ);

        conv_kernel<<<gConv, TPB>>>(zx0, m_cw + (size_t)(i * 2 + 0) * CONVD * 4,
                                    m_cb + (size_t)(i * 2 + 0) * CONVD, xc0);
        conv_kernel<<<gConv, TPB>>>(zx1, m_cw + (size_t)(i * 2 + 1) * CONVD * 4,
                                    m_cb + (size_t)(i * 2 + 1) * CONVD, xc1);

        dt_kernel<<<gDt, TPB>>>(zx0, m_dtb + (i * 2 + 0) * NHEADS,
                                m_Alog + (i * 2 + 0) * NHEADS, dt0, dA0);
        dt_kernel<<<gDt, TPB>>>(zx1, m_dtb + (i * 2 + 1) * NHEADS,
                                m_Alog + (i * 2 + 1) * NHEADS, dt1, dA1);

        scan_kernel<<<dim3(BATCH * NHEADS, 2), 256>>>(
            xc0, xc1, zx0, zx1, dt0, dt1, dA0, dA1, m_D + i * 2 * NHEADS, y0, y1);

        rmsnorm_kernel<<<ML, 256>>>(y0, m_norm + (size_t)(i * 2 + 0) * DINNER);
        rmsnorm_kernel<<<ML, 256>>>(y1, m_norm + (size_t)(i * 2 + 1) * DINNER);

        // fwd out-proj writes straight into comb[:, :512]; bwd into dr1 then flip-cat
        tf32gemm<<<ggrid(HDIM), 256, GEMM_SMEM>>>(
            y0, m_Wout + (size_t)(i * 2 + 0) * HDIM * DINNER, nullptr, cb, ML, HDIM, DINNER, DINNER);
        tf32gemm<<<ggrid(HDIM), 256, GEMM_SMEM>>>(
            y1, m_Wout + (size_t)(i * 2 + 1) * HDIM * DINNER, nullptr, dr1, ML, HDIM, DINNER, HDIM);

        flipcat_kernel<<<gEl, TPB>>>(dr1, lens, cb);
        tf32gemm<<<ggrid(HDIM), 256, GEMM_SMEM>>>(
            cb, blk_Wo + (size_t)i * HDIM * DINNER, blk_bo + i * HDIM, ot, ML, HDIM, DINNER, HDIM);
        addln_kernel<<<ML, 128>>>(ot, h, ln_g + i * HDIM, ln_b + i * HDIM);
    }

    tf32gemm<<<ggrid(2 * HDIM), 256, GEMM_SMEM>>>(h, W_enc, b_enc, outp, ML, 2 * HDIM, HDIM, 2 * HDIM);

    pool_kernel<<<BATCH * 32, 256>>>(outp, lens, pl);
    adapter_kernel<<<(BATCH * HDIM) / 8, 256>>>(pl, W_ad, b_ad,
                                                outp + (size_t)ML * 2 * HDIM);
}